// round 8
// baseline (speedup 1.0000x reference)
#include <cuda_runtime.h>
#include <stdint.h>
#include <math.h>

#define HH   128
#define NHD  2
#define HDd  64
#define BB   8
#define LLs  200
#define TVC  32
#define NROWS (BB*LLs)   // 1600
#define KSTR 68          // smem row stride: float4-aligned, conflict-free here

typedef unsigned long long ull;

// scratch (device globals: no allocation allowed)
__device__ float g_q  [NROWS*HH];
__device__ float g_kk [NROWS*HH];
__device__ float g_vv [NROWS*HH];
__device__ float g_ctx[NROWS*HH];

// ---- helpers --------------------------------------------------------------
__device__ __forceinline__ void cp16(uint32_t s, const void* g) {
    asm volatile("cp.async.cg.shared.global [%0], [%1], 16;" :: "r"(s), "l"(g));
}
__device__ __forceinline__ void cp_commit_wait() {
    asm volatile("cp.async.commit_group;");
    asm volatile("cp.async.wait_group 0;" ::: "memory");
}
__device__ __forceinline__ ull pk2(float x) {
    ull r; asm("mov.b64 %0,{%1,%1};" : "=l"(r) : "f"(x)); return r;
}
__device__ __forceinline__ void fma2(ull& d, ull a, ull b) {
    asm("fma.rn.f32x2 %0,%1,%2,%0;" : "+l"(d) : "l"(a), "l"(b));
}
__device__ __forceinline__ float f2lo(ull v) {
    float a, b; asm("mov.b64 {%0,%1},%2;" : "=f"(a), "=f"(b) : "l"(v)); return a;
}
__device__ __forceinline__ float f2hi(ull v) {
    float a, b; asm("mov.b64 {%0,%1},%2;" : "=f"(a), "=f"(b) : "l"(v)); return b;
}

extern __shared__ float smem_dyn[];

// ---------------------------------------------------------------------------
// Kernel 1: fused QKV projection (unchanged from R7)
// ---------------------------------------------------------------------------
#define PSTEP(comp, j)                                                        \
    {                                                                         \
        ull wv = wsu[(i0 + (j))*32 + lane];                                   \
        fma2(a0, pk2(xr0.comp), wv);                                          \
        fma2(a1, pk2(xr1.comp), wv);                                          \
        fma2(a2, pk2(xr2.comp), wv);                                          \
        fma2(a3, pk2(xr3.comp), wv);                                          \
    }

__global__ void __launch_bounds__(256, 2)
proj_kernel(const float* __restrict__ X,
            const float* __restrict__ Wq, const float* __restrict__ bq,
            const float* __restrict__ Wk, const float* __restrict__ bk,
            const float* __restrict__ Wv, const float* __restrict__ bv,
            const float* __restrict__ kpos, const float* __restrict__ vpos)
{
    const int m    = blockIdx.y;
    const int hf   = blockIdx.z;
    const int rb   = blockIdx.x * 32;
    const int tid  = threadIdx.x;
    const int lane = tid & 31;
    const int wid  = tid >> 5;

    float* xs = smem_dyn;          // 32*128
    float* ws = smem_dyn + 4096;   // 128*64

    const float* W    = (m==0) ? Wq : (m==1 ? Wk : Wv);
    const float* bias = (m==0) ? bq : (m==1 ? bk : bv);

    {
        uint32_t xs_s = (uint32_t)__cvta_generic_to_shared(xs);
        uint32_t ws_s = (uint32_t)__cvta_generic_to_shared(ws);
        #pragma unroll
        for (int j = 0; j < 4; j++) {
            int c = tid + 256*j;
            cp16(xs_s + c*16, X + (size_t)rb*128 + c*4);
        }
        #pragma unroll
        for (int j = 0; j < 8; j++) {
            int c = tid + 256*j;
            int i = c >> 4, sub = c & 15;
            cp16(ws_s + (i*64 + sub*4)*4, W + i*128 + hf*64 + sub*4);
        }
        cp_commit_wait();
    }
    __syncthreads();

    const int r0 = wid * 4;
    ull a0=0, a1=0, a2=0, a3=0;
    const ull* wsu = (const ull*)ws;

    for (int i0 = 0; i0 < 128; i0 += 4) {
        float4 xr0 = *(const float4*)(xs + (r0+0)*128 + i0);
        float4 xr1 = *(const float4*)(xs + (r0+1)*128 + i0);
        float4 xr2 = *(const float4*)(xs + (r0+2)*128 + i0);
        float4 xr3 = *(const float4*)(xs + (r0+3)*128 + i0);
        PSTEP(x, 0)
        PSTEP(y, 1)
        PSTEP(z, 2)
        PSTEP(w, 3)
    }

    const int col = hf*64 + lane*2;
    float2 bz = *(const float2*)(bias + col);
    float* outg = (m==0) ? g_q : (m==1 ? g_kk : g_vv);
    const float* pos = (m==1) ? kpos : vpos;

    ull acc[4] = {a0, a1, a2, a3};
    #pragma unroll
    for (int r = 0; r < 4; r++) {
        const int gr = rb + r0 + r;
        float2 o;
        o.x = f2lo(acc[r]) + bz.x;
        o.y = f2hi(acc[r]) + bz.y;
        if (m != 0) {
            float2 p = *(const float2*)(pos + (gr % LLs)*128 + col);
            o.x += p.x; o.y += p.y;
        }
        *(float2*)(outg + (size_t)gr*128 + col) = o;
    }
}

// ---------------------------------------------------------------------------
// Kernel 2: attention.  grid (8 q-tiles, NH, B), block 256.
// Telescoping-prefix binning + normalize-at-end softmax + staged mask.
// ---------------------------------------------------------------------------
// smem float offsets:
//   kk 0 (13600)  vv 13600  kt 27200 (2176)  vt 29376 (2176)
//   tv 31552 (200 int)  qall 31752 (1600)  tsall 33352 (800)
//   msk 34152 (5000)  e4 39152 (800)  eb 39952 (200)
//   ix4 40152 (804 -> pad 808)  ixb 40960 (200)
//   cbin 41160 (256)  wtot 41416 (48)
//   pA 41464 (2560)  pB 44024 (2560)  red 46584 (96)
#define SMEM_FLOATS 46688

__global__ void attn_kernel(const float* __restrict__ maskg,
                            const void*  __restrict__ tsq,
                            const float* __restrict__ KTg,
                            const float* __restrict__ VTg)
{
    float* sm = smem_dyn;
    const int qt   = blockIdx.x;
    const int h    = blockIdx.y;
    const int b    = blockIdx.z;
    const int tid  = threadIdx.x;
    const int lane = tid & 31;
    const int wid  = tid >> 5;

    float* kk    = sm;
    float* vv    = sm + 13600;
    float* kt    = sm + 27200;
    float* vt    = sm + 29376;
    int*   tv    = (int*)(sm + 31552);
    float* qall  = sm + 31752;
    float* tsall = sm + 33352;
    float* msk   = sm + 34152;
    float* e4    = sm + 39152;
    float* eb    = sm + 39952;
    int*   ix4   = (int*)(sm + 40152);
    int*   ixb   = (int*)(sm + 40960);
    float* cbin  = sm + 41160;           // [32 w][8]
    float* wtot  = sm + 41416;           // [5 q][8 warps]
    float* pA    = sm + 41464;           // e.v partials: 5*8*32 float2
    float* pB    = sm + 44024;           // time partials
    float* red   = sm + 46584;

    // ---- stage mask tile via cp.async (25 q x 200 k) ------------------------
    {
        uint32_t msk_s = (uint32_t)__cvta_generic_to_shared(msk);
        const float* mbase = maskg + ((size_t)(b*LLs) + qt*25)*LLs;
        for (int c = tid; c < 1250; c += 256)
            cp16(msk_s + c*16, mbase + c*4);
    }

    // ---- stage K,V head slices (float4, stride 68) --------------------------
    const float* kkg = g_kk + (size_t)(b*LLs)*HH + h*HDd;
    const float* vvg = g_vv + (size_t)(b*LLs)*HH + h*HDd;
    for (int idx = tid; idx < LLs*16; idx += 256) {
        int k = idx >> 4, d4 = idx & 15;
        ((float4*)(kk + k*KSTR))[d4] = ((const float4*)(kkg + k*HH))[d4];
        ((float4*)(vv + k*KSTR))[d4] = ((const float4*)(vvg + k*HH))[d4];
    }
    for (int idx = tid; idx < TVC*16; idx += 256) {
        int w = idx >> 4, d4 = idx & 15;
        ((float4*)(kt + w*KSTR))[d4] = ((const float4*)(KTg + w*HH + h*HDd))[d4];
        ((float4*)(vt + w*KSTR))[d4] = ((const float4*)(VTg + w*HH + h*HDd))[d4];
    }
    // time values: int64 vs int32 detection (word 199 = high word if int64)
    {
        const int* t32 = (const int*)tsq;
        bool is64 = (t32[199] == 0);
        for (int k = tid; k < LLs; k += 256)
            tv[k] = is64 ? (int)((const long long*)tsq)[b*LLs + k]
                         : t32[b*LLs + k];
    }
    // q rows
    {
        const float* qg = g_q + (size_t)(b*LLs)*HH + h*HDd;
        for (int idx = tid; idx < 25*16; idx += 256) {
            int q = idx >> 4, d4 = idx & 15;
            ((float4*)(qall + q*64))[d4] = ((const float4*)(qg + (qt*25+q)*HH))[d4];
        }
    }
    cp_commit_wait();
    __syncthreads();

    // ---- ts_all[q][w] = q . KT[w] -------------------------------------------
    for (int i = tid; i < 25*32; i += 256) {
        int q = i >> 5, w = i & 31;
        const ull* q2  = (const ull*)(qall + q*64);
        const ull* ktr = (const ull*)(kt + w*KSTR);
        ull a = 0;
        #pragma unroll
        for (int j = 0; j < 32; j++) fma2(a, q2[j], ktr[j]);
        tsall[i] = f2lo(a) + f2hi(a);
    }
    __syncthreads();

    const int  k      = tid;
    const bool active = (k < LLs);
    const int  kid    = active ? k : (LLs-1);

    for (int it = 0; it < 5; it++) {
        const int q0    = it*5;
        const int qbase = qt*25 + q0;

        cbin[tid] = 0.f;   // 256 floats, reset bins (safe: read done pre-B3 prev iter)

        // ---- phase A: scores, e, stores, warp e-sums ------------------------
        float sv[5], ev[5], Pv[5];
        int   ixv[5];

        {
            ull a2[5];
            #pragma unroll
            for (int q = 0; q < 5; q++) a2[q] = 0;
            const ulonglong2* kr2 = (const ulonglong2*)(kk + kid*KSTR);
            #pragma unroll
            for (int j = 0; j < 16; j++) {
                ulonglong2 y = kr2[j];
                #pragma unroll
                for (int q = 0; q < 5; q++) {
                    ulonglong2 x = ((const ulonglong2*)(qall + (q0+q)*64))[j];
                    fma2(a2[q], x.x, y.x);
                    fma2(a2[q], x.y, y.y);
                }
            }
            const int tk = tv[kid];
            #pragma unroll
            for (int q = 0; q < 5; q++) {
                float aq = f2lo(a2[q]) + f2hi(a2[q]);
                int dt = tv[qbase+q] - tk; if (dt < 0) dt = -dt;
                int ixq = (int)log1pf((float)dt);
                float s = (aq + tsall[(q0+q)*32 + ixq])*0.125f + msk[(q0+q)*200 + kid];
                sv[q]  = active ? s : 0.f;
                ixv[q] = ixq;
                ev[q]  = active ? __expf(s) : 0.f;
            }
            if (active) {
                ((float4*)e4)[k] = make_float4(ev[0], ev[1], ev[2], ev[3]);
                eb[k] = ev[4];
                ((int4*)ix4)[k] = make_int4(ixv[0], ixv[1], ixv[2], ixv[3]);
                ixb[k] = ixv[4];
            }
        }

        // warp e-sums
        #pragma unroll
        for (int q = 0; q < 5; q++) {
            float se = ev[q];
            #pragma unroll
            for (int o = 16; o > 0; o >>= 1)
                se += __shfl_xor_sync(0xFFFFFFFFu, se, o);
            if (lane == 0) red[q*8 + wid] = se;
        }
        // warp inclusive prefix of s
        #pragma unroll
        for (int q = 0; q < 5; q++) {
            float P = sv[q];
            #pragma unroll
            for (int o = 1; o < 32; o <<= 1) {
                float t = __shfl_up_sync(0xFFFFFFFFu, P, o);
                if (lane >= o) P += t;
            }
            Pv[q] = P;
            if (lane == 31) wtot[q*8 + wid] = P;
        }
        __syncthreads();   // B1

        if (tid < 5) {
            float se = 0.f;
            #pragma unroll
            for (int i = 0; i < 8; i++) se += red[tid*8 + i];
            red[48 + tid] = 1.f / se;
        }

        // cross-warp prefix offsets
        #pragma unroll
        for (int q = 0; q < 5; q++) {
            float off = 0.f;
            #pragma unroll
            for (int w = 0; w < 8; w++)
                if (w < wid) off += wtot[q*8 + w];
            Pv[q] += off;
        }

        // ---- telescope binning: boundaries -> atomics -----------------------
        if (active) {
            int nxt[5];
            if (k < LLs-1) {
                int4 ivn = ((const int4*)ix4)[k+1];
                nxt[0]=ivn.x; nxt[1]=ivn.y; nxt[2]=ivn.z; nxt[3]=ivn.w;
                nxt[4]=ixb[k+1];
            }
            #pragma unroll
            for (int q = 0; q < 5; q++) {
                if (k == LLs-1) {
                    atomicAdd(&cbin[ixv[q]*8 + q], Pv[q]);
                } else if (ixv[q] != nxt[q]) {
                    atomicAdd(&cbin[ixv[q]*8 + q],  Pv[q]);
                    atomicAdd(&cbin[nxt[q]*8 + q], -Pv[q]);
                }
            }
        }
        __syncthreads();   // B2: atomics + e4 stores visible

        // ---- ctx partials: pA = sum_k e*v ; pB = sum_w cbin*vt --------------
        {
            const int kc = wid, d2 = lane;
            float2 acc[5];
            #pragma unroll
            for (int q = 0; q < 5; q++) { acc[q].x = 0.f; acc[q].y = 0.f; }
            const int kb = kc*25;
            #pragma unroll 5
            for (int kk2 = 0; kk2 < 25; kk2++) {
                int kx = kb + kk2;
                float2 v  = *(const float2*)(vv + kx*KSTR + 2*d2);
                float4 e_ = ((const float4*)e4)[kx];
                float  eB = eb[kx];
                acc[0].x += e_.x*v.x; acc[0].y += e_.x*v.y;
                acc[1].x += e_.y*v.x; acc[1].y += e_.y*v.y;
                acc[2].x += e_.z*v.x; acc[2].y += e_.z*v.y;
                acc[3].x += e_.w*v.x; acc[3].y += e_.w*v.y;
                acc[4].x += eB  *v.x; acc[4].y += eB  *v.y;
            }
            float2 tacc[5];
            #pragma unroll
            for (int q = 0; q < 5; q++) { tacc[q].x = 0.f; tacc[q].y = 0.f; }
            #pragma unroll
            for (int w = kc*4; w < kc*4 + 4; w++) {
                float2 tvv = *(const float2*)(vt + w*KSTR + 2*d2);
                float4 c4  = *(const float4*)(cbin + w*8);
                float  cB  = cbin[w*8 + 4];
                tacc[0].x += c4.x*tvv.x; tacc[0].y += c4.x*tvv.y;
                tacc[1].x += c4.y*tvv.x; tacc[1].y += c4.y*tvv.y;
                tacc[2].x += c4.z*tvv.x; tacc[2].y += c4.z*tvv.y;
                tacc[3].x += c4.w*tvv.x; tacc[3].y += c4.w*tvv.y;
                tacc[4].x += cB  *tvv.x; tacc[4].y += cB  *tvv.y;
            }
            #pragma unroll
            for (int q = 0; q < 5; q++) {
                ((float2*)pA)[(q*8 + kc)*32 + d2] = acc[q];
                ((float2*)pB)[(q*8 + kc)*32 + d2] = tacc[q];
            }
        }
        __syncthreads();   // B3

        if (tid < 160) {
            int q = tid >> 5, d2 = tid & 31;
            float rs = red[48 + q];
            float2 A; A.x = 0.f; A.y = 0.f;
            float2 T; T.x = 0.f; T.y = 0.f;
            #pragma unroll
            for (int kc = 0; kc < 8; kc++) {
                float2 x = ((float2*)pA)[(q*8 + kc)*32 + d2];
                float2 y = ((float2*)pB)[(q*8 + kc)*32 + d2];
                A.x += x.x; A.y += x.y;
                T.x += y.x; T.y += y.y;
            }
            float2 o;
            o.x = A.x*rs + T.x;
            o.y = A.y*rs + T.y;
            *(float2*)(g_ctx + ((size_t)(b*LLs) + qbase + q)*HH + h*HDd + 2*d2) = o;
        }
        // no trailing barrier needed: next iter's conflicting writes are
        // gated behind its own B1/B2 which the final-reduce threads must reach.
    }
}

// ---------------------------------------------------------------------------
// Kernel 3: output projection + bias + residual + LayerNorm (unchanged R7)
// ---------------------------------------------------------------------------
__global__ void __launch_bounds__(256, 1)
out_ln_kernel(const float* __restrict__ X,
              const float* __restrict__ Wd, const float* __restrict__ bd,
              const float* __restrict__ lng, const float* __restrict__ lnb,
              float* __restrict__ out)
{
    const int rb   = blockIdx.x * 16;
    const int tid  = threadIdx.x;
    const int lane = tid & 31;
    const int wid  = tid >> 5;

    float* xs = smem_dyn;          // 16*128
    float* ws = smem_dyn + 2048;   // 128*128

    {
        uint32_t xs_s = (uint32_t)__cvta_generic_to_shared(xs);
        uint32_t ws_s = (uint32_t)__cvta_generic_to_shared(ws);
        #pragma unroll
        for (int j = 0; j < 2; j++) {
            int c = tid + 256*j;
            cp16(xs_s + c*16, g_ctx + (size_t)rb*128 + c*4);
        }
        #pragma unroll
        for (int j = 0; j < 16; j++) {
            int c = tid + 256*j;
            cp16(ws_s + c*16, Wd + c*4);
        }
        cp_commit_wait();
    }
    __syncthreads();

    const int r0 = wid * 2;
    ull a00=0, a01=0, a10=0, a11=0;
    const ulonglong2* ws2 = (const ulonglong2*)ws;

    #define OSTEP(comp, j)                                                    \
        {                                                                     \
            ulonglong2 wv = ws2[(i0 + (j))*32 + lane];                        \
            ull p0 = pk2(xr0.comp), p1 = pk2(xr1.comp);                       \
            fma2(a00, p0, wv.x); fma2(a01, p0, wv.y);                         \
            fma2(a10, p1, wv.x); fma2(a11, p1, wv.y);                         \
        }

    for (int i0 = 0; i0 < 128; i0 += 4) {
        float4 xr0 = *(const float4*)(xs + (r0+0)*128 + i0);
        float4 xr1 = *(const float4*)(xs + (r0+1)*128 + i0);
        OSTEP(x, 0)
        OSTEP(y, 1)
        OSTEP(z, 2)
        OSTEP(w, 3)
    }
    #undef OSTEP

    float4 bz = ((const float4*)bd)[lane];
    float4 g  = ((const float4*)lng)[lane];
    float4 bb = ((const float4*)lnb)[lane];

    ull aL[2] = {a00, a10};
    ull aH[2] = {a01, a11};

    #pragma unroll
    for (int r = 0; r < 2; r++) {
        const int gr = rb + r0 + r;
        float4 xg = ((const float4*)X)[(size_t)gr*32 + lane];
        float4 hv;
        hv.x = f2lo(aL[r]) + bz.x + xg.x;
        hv.y = f2hi(aL[r]) + bz.y + xg.y;
        hv.z = f2lo(aH[r]) + bz.z + xg.z;
        hv.w = f2hi(aH[r]) + bz.w + xg.w;

        float s  = hv.x + hv.y + hv.z + hv.w;
        float s2 = hv.x*hv.x + hv.y*hv.y + hv.z*hv.z + hv.w*hv.w;
        #pragma unroll
        for (int o = 16; o > 0; o >>= 1) {
            s  += __shfl_xor_sync(0xFFFFFFFFu, s,  o);
            s2 += __shfl_xor_sync(0xFFFFFFFFu, s2, o);
        }
        float mu  = s * (1.f/128.f);
        float var = s2 * (1.f/128.f) - mu*mu;
        float is  = rsqrtf(fmaxf(var, 0.f) + 1e-12f);

        float4 o4;
        o4.x = (hv.x - mu)*is*g.x + bb.x;
        o4.y = (hv.y - mu)*is*g.y + bb.y;
        o4.z = (hv.z - mu)*is*g.z + bb.z;
        o4.w = (hv.w - mu)*is*g.w + bb.w;
        ((float4*)out)[(size_t)gr*32 + lane] = o4;
    }
}

// ---------------------------------------------------------------------------
extern "C" void kernel_launch(void* const* d_in, const int* in_sizes, int n_in,
                              void* d_out, int out_size)
{
    const float* X    = (const float*)d_in[0];
    const void*  tsq  = d_in[1];
    const float* mask = (const float*)d_in[2];
    const float* Wq   = (const float*)d_in[3];
    const float* bq   = (const float*)d_in[4];
    const float* Wk   = (const float*)d_in[5];
    const float* bk   = (const float*)d_in[6];
    const float* Wv   = (const float*)d_in[7];
    const float* bv   = (const float*)d_in[8];
    const float* Wd   = (const float*)d_in[9];
    const float* bd   = (const float*)d_in[10];
    const float* lng  = (const float*)d_in[11];
    const float* lnb  = (const float*)d_in[12];
    const float* KT   = (const float*)d_in[13];
    const float* VT   = (const float*)d_in[14];
    const float* kp   = (const float*)d_in[15];
    const float* vp   = (const float*)d_in[16];

    const size_t smem_proj = (4096 + 8192)  * sizeof(float);  // 48KB
    const size_t smem_out  = (2048 + 16384) * sizeof(float);  // 72KB
    const size_t smem_attn = SMEM_FLOATS * sizeof(float);     // ~182KB

    cudaFuncSetAttribute(proj_kernel,   cudaFuncAttributeMaxDynamicSharedMemorySize, (int)smem_proj);
    cudaFuncSetAttribute(out_ln_kernel, cudaFuncAttributeMaxDynamicSharedMemorySize, (int)smem_out);
    cudaFuncSetAttribute(attn_kernel,   cudaFuncAttributeMaxDynamicSharedMemorySize, (int)smem_attn);

    proj_kernel<<<dim3(50, 3, 2), 256, smem_proj>>>(X, Wq, bq, Wk, bk, Wv, bv, kp, vp);
    attn_kernel<<<dim3(8, NHD, BB), 256, smem_attn>>>(mask, tsq, KT, VT);
    out_ln_kernel<<<100, 256, smem_out>>>(X, Wd, bd, lng, lnb, (float*)d_out);
}